// round 2
// baseline (speedup 1.0000x reference)
#include <cuda_runtime.h>
#include <math_constants.h>

#define NB 32
#define NT 512
#define ND 512
#define NV 1024
#define NL 128
#define NS 257      // 2*NL+1
#define SPAD 288    // padded S stride
#define NM (NB*NT)  // 16384 rows

// Scratch (allocation-free per harness rules)
__device__ float g_logits[(size_t)NM * NV];   // 64 MB
__device__ float g_pext[(size_t)NM * SPAD];   // 18.9 MB
__device__ float g_loss[NB];

// ---------------------------------------------------------------------------
// Kernel 1: logits = x @ W + b   (fp32 SIMT, 128x128x8 tiles, 8x8 per thread)
// ---------------------------------------------------------------------------
__global__ __launch_bounds__(256) void gemm_kernel(const float* __restrict__ A,
                                                   const float* __restrict__ B,
                                                   const float* __restrict__ bias) {
    const int K = ND, N = NV;
    __shared__ float As[8][128];
    __shared__ float Bs[8][128];
    int tid = threadIdx.x;
    int bx = blockIdx.x, by = blockIdx.y;
    const float* Ab = A + (size_t)by * 128 * K;
    const float* Bb = B + bx * 128;
    float* Cb = g_logits + (size_t)by * 128 * N + bx * 128;

    int arow = tid >> 1, acol = (tid & 1) * 4;
    int brow = tid >> 5, bcol = (tid & 31) * 4;
    int ty = tid >> 4, tx = tid & 15;

    float acc[8][8];
#pragma unroll
    for (int i = 0; i < 8; i++)
#pragma unroll
        for (int j = 0; j < 8; j++) acc[i][j] = 0.f;

    for (int k0 = 0; k0 < K; k0 += 8) {
        float4 av = *(const float4*)(Ab + (size_t)arow * K + k0 + acol);
        As[acol + 0][arow] = av.x;
        As[acol + 1][arow] = av.y;
        As[acol + 2][arow] = av.z;
        As[acol + 3][arow] = av.w;
        *(float4*)(&Bs[brow][bcol]) = *(const float4*)(Bb + (size_t)(k0 + brow) * N + bcol);
        __syncthreads();
#pragma unroll
        for (int kk = 0; kk < 8; kk++) {
            float ra[8], rb[8];
            *(float4*)&ra[0] = *(const float4*)&As[kk][ty * 8];
            *(float4*)&ra[4] = *(const float4*)&As[kk][ty * 8 + 4];
            *(float4*)&rb[0] = *(const float4*)&Bs[kk][tx * 8];
            *(float4*)&rb[4] = *(const float4*)&Bs[kk][tx * 8 + 4];
#pragma unroll
            for (int i = 0; i < 8; i++)
#pragma unroll
                for (int j = 0; j < 8; j++) acc[i][j] += ra[i] * rb[j];
        }
        __syncthreads();
    }

    int col0 = bx * 128 + tx * 8;
#pragma unroll
    for (int i = 0; i < 8; i++) {
#pragma unroll
        for (int j0 = 0; j0 < 8; j0 += 4) {
            float4 o;
            o.x = acc[i][j0 + 0] + bias[col0 + j0 + 0];
            o.y = acc[i][j0 + 1] + bias[col0 + j0 + 1];
            o.z = acc[i][j0 + 2] + bias[col0 + j0 + 2];
            o.w = acc[i][j0 + 3] + bias[col0 + j0 + 3];
            *(float4*)(Cb + (size_t)(ty * 8 + i) * N + tx * 8 + j0) = o;
        }
    }
}

// ---------------------------------------------------------------------------
// Kernel 2: per-row softmax over V, emit PROBABILITIES at extended labels
//           p_ext[row][s]: even s -> p(blank), odd s -> p(target[(s-1)/2])
// ---------------------------------------------------------------------------
__global__ __launch_bounds__(128) void softmax_kernel(const int* __restrict__ target) {
    int warp = threadIdx.x >> 5, lane = threadIdx.x & 31;
    int row = blockIdx.x * 4 + warp;          // 0..16383
    int b = row >> 9;                          // row / 512
    const float* lg = g_logits + (size_t)row * NV;

    float m = -CUDART_INF_F;
    float4 v[8];
#pragma unroll
    for (int i = 0; i < 8; i++) {
        v[i] = *(const float4*)(lg + i * 128 + lane * 4);
        m = fmaxf(m, fmaxf(fmaxf(v[i].x, v[i].y), fmaxf(v[i].z, v[i].w)));
    }
#pragma unroll
    for (int o = 16; o > 0; o >>= 1) m = fmaxf(m, __shfl_xor_sync(0xffffffffu, m, o));

    float se = 0.f;
#pragma unroll
    for (int i = 0; i < 8; i++)
        se += __expf(v[i].x - m) + __expf(v[i].y - m) + __expf(v[i].z - m) + __expf(v[i].w - m);
#pragma unroll
    for (int o = 16; o > 0; o >>= 1) se += __shfl_xor_sync(0xffffffffu, se, o);

    float inv = 1.f / se;
    float pblank = __expf(lg[0] - m) * inv;

    float* P = g_pext + (size_t)row * SPAD;
    const int* tg = target + b * NL;
    for (int j = lane; j < NL; j += 32) {
        int lab = tg[j];
        P[2 * j + 1] = __expf(lg[lab] - m) * inv;
    }
    for (int j = lane; j <= NL; j += 32) P[2 * j] = pblank;
    if (lane < 31) P[NS + lane] = 0.f;   // zero the pad (s = 257..287)
}

// ---------------------------------------------------------------------------
// Kernel 3: CTC forward recursion in probability domain with rescaling.
//           One warp per batch; lane owns 9 contiguous s positions.
// ---------------------------------------------------------------------------
__global__ __launch_bounds__(32) void ctc_kernel(const int* __restrict__ target,
                                                 const int* __restrict__ in_len,
                                                 const int* __restrict__ tgt_len) {
    int b = blockIdx.x;
    int lane = threadIdx.x;
    int s0 = lane * 9;
    const int* tg = target + b * NL;

    // skip flags: odd s >= 3 where target[(s-1)/2] != target[(s-3)/2]
    unsigned skipm = 0;
#pragma unroll
    for (int k = 0; k < 9; k++) {
        int s = s0 + k;
        if (s >= 3 && s < NS && (s & 1)) {
            int j = (s - 1) >> 1;
            if (tg[j] != tg[j - 1]) skipm |= (1u << k);
        }
    }

    const float* P = g_pext + (size_t)b * NT * SPAD;
    int TL = in_len[b];
    int tl = tgt_len[b];
    int send1 = 2 * tl - 1, send2 = 2 * tl;

    float a[9];
#pragma unroll
    for (int k = 0; k < 9; k++) {
        int s = s0 + k;
        float p = (s < NS) ? P[s] : 0.f;
        a[k] = (s < 2) ? p : 0.f;
    }

    float logscale = 0.f;
    float ll = -CUDART_INF_F;

    if (TL == 1) {
        float part = 0.f;
#pragma unroll
        for (int k = 0; k < 9; k++) {
            int s = s0 + k;
            part += (s == send1 || s == send2) ? a[k] : 0.f;
        }
#pragma unroll
        for (int o = 16; o > 0; o >>= 1) part += __shfl_xor_sync(0xffffffffu, part, o);
        ll = __logf(part);
    }

    // prefetch pipeline: pA = p(t), pB = p(t+1)
    float pA[9], pB[9];
#pragma unroll
    for (int k = 0; k < 9; k++) { int s = s0 + k; pA[k] = (s < NS) ? P[SPAD + s] : 0.f; }
#pragma unroll
    for (int k = 0; k < 9; k++) { int s = s0 + k; pB[k] = (s < NS) ? P[2 * SPAD + s] : 0.f; }

    for (int t = 1; t < NT; t++) {
        float pN[9];
        if (t + 2 < NT) {
            const float* Pt = P + (size_t)(t + 2) * SPAD;
#pragma unroll
            for (int k = 0; k < 9; k++) { int s = s0 + k; pN[k] = (s < NS) ? Pt[s] : 0.f; }
        } else {
#pragma unroll
            for (int k = 0; k < 9; k++) pN[k] = 0.f;
        }

        float up1 = __shfl_up_sync(0xffffffffu, a[8], 1);  // s0-1
        float up2 = __shfl_up_sync(0xffffffffu, a[7], 1);  // s0-2
        if (lane == 0) { up1 = 0.f; up2 = 0.f; }

        float na[9];
#pragma unroll
        for (int k = 0; k < 9; k++) {
            float sm1 = (k >= 1) ? a[k - 1] : up1;
            float sm2 = (k >= 2) ? a[k - 2] : ((k == 1) ? up1 : up2);
            float c = a[k] + sm1;
            if ((skipm >> k) & 1u) c += sm2;
            na[k] = c * pA[k];
        }
#pragma unroll
        for (int k = 0; k < 9; k++) a[k] = na[k];

        if (t == TL - 1) {
            float part = 0.f;
#pragma unroll
            for (int k = 0; k < 9; k++) {
                int s = s0 + k;
                part += (s == send1 || s == send2) ? a[k] : 0.f;
            }
#pragma unroll
            for (int o = 16; o > 0; o >>= 1) part += __shfl_xor_sync(0xffffffffu, part, o);
            ll = logscale + __logf(part);
        }

        if ((t & 3) == 3) {
            float tot = 0.f;
#pragma unroll
            for (int k = 0; k < 9; k++) tot += a[k];
#pragma unroll
            for (int o = 16; o > 0; o >>= 1) tot += __shfl_xor_sync(0xffffffffu, tot, o);
            if (tot > 0.f) {
                float sc = 1.f / tot;
                logscale += __logf(tot);
#pragma unroll
                for (int k = 0; k < 9; k++) a[k] *= sc;
            }
        }

#pragma unroll
        for (int k = 0; k < 9; k++) { pA[k] = pB[k]; pB[k] = pN[k]; }
    }

    if (lane == 0) {
        float nll = -ll;
        if (!(nll < 1e29f)) nll = 0.f;   // zero_infinity (also catches NaN)
        g_loss[b] = nll / fmaxf((float)tl, 1.f);
    }
}

// ---------------------------------------------------------------------------
// Kernel 4: mean over batch
// ---------------------------------------------------------------------------
__global__ void reduce_kernel(float* __restrict__ out) {
    int lane = threadIdx.x;
    float v = (lane < NB) ? g_loss[lane] : 0.f;
#pragma unroll
    for (int o = 16; o > 0; o >>= 1) v += __shfl_xor_sync(0xffffffffu, v, o);
    if (lane == 0) out[0] = v * (1.f / NB);
}

extern "C" void kernel_launch(void* const* d_in, const int* in_sizes, int n_in,
                              void* d_out, int out_size) {
    const float* x = (const float*)d_in[0];        // [B,T,D]
    const float* W = (const float*)d_in[1];        // [D,V]
    const float* bias = (const float*)d_in[2];     // [V]
    const int* target = (const int*)d_in[3];       // [B,L]
    const int* in_len = (const int*)d_in[4];       // [B]
    const int* tgt_len = (const int*)d_in[5];      // [B]

    dim3 gg(NV / 128, NM / 128);
    gemm_kernel<<<gg, 256>>>(x, W, bias);
    softmax_kernel<<<NM / 4, 128>>>(target);
    ctc_kernel<<<NB, 32>>>(target, in_len, tgt_len);
    reduce_kernel<<<1, 32>>>((float*)d_out);
}

// round 3
// speedup vs baseline: 1.0016x; 1.0016x over previous
#include <cuda_runtime.h>
#include <math_constants.h>

#define NB 32
#define NT 512
#define ND 512
#define NV 1024
#define NL 128
#define NS 257      // 2*NL+1
#define SPAD 288    // padded S stride
#define NM (NB*NT)  // 16384 rows

// Scratch (allocation-free per harness rules)
__device__ float g_logits[(size_t)NM * NV];   // 64 MB
__device__ float g_pext[(size_t)NM * SPAD];   // 18.9 MB
__device__ float g_loss[NB];

// ---------------------------------------------------------------------------
// Kernel 1: logits = x @ W + b   (fp32 SIMT, 128x128x8 tiles, 8x8 per thread)
// ---------------------------------------------------------------------------
__global__ __launch_bounds__(256) void gemm_kernel(const float* __restrict__ A,
                                                   const float* __restrict__ B,
                                                   const float* __restrict__ bias) {
    const int K = ND, N = NV;
    __shared__ float As[8][128];
    __shared__ float Bs[8][128];
    int tid = threadIdx.x;
    int bx = blockIdx.x, by = blockIdx.y;
    const float* Ab = A + (size_t)by * 128 * K;
    const float* Bb = B + bx * 128;
    float* Cb = g_logits + (size_t)by * 128 * N + bx * 128;

    int arow = tid >> 1, acol = (tid & 1) * 4;
    int brow = tid >> 5, bcol = (tid & 31) * 4;
    int ty = tid >> 4, tx = tid & 15;

    float acc[8][8];
#pragma unroll
    for (int i = 0; i < 8; i++)
#pragma unroll
        for (int j = 0; j < 8; j++) acc[i][j] = 0.f;

    for (int k0 = 0; k0 < K; k0 += 8) {
        float4 av = *(const float4*)(Ab + (size_t)arow * K + k0 + acol);
        As[acol + 0][arow] = av.x;
        As[acol + 1][arow] = av.y;
        As[acol + 2][arow] = av.z;
        As[acol + 3][arow] = av.w;
        *(float4*)(&Bs[brow][bcol]) = *(const float4*)(Bb + (size_t)(k0 + brow) * N + bcol);
        __syncthreads();
#pragma unroll
        for (int kk = 0; kk < 8; kk++) {
            float ra[8], rb[8];
            *(float4*)&ra[0] = *(const float4*)&As[kk][ty * 8];
            *(float4*)&ra[4] = *(const float4*)&As[kk][ty * 8 + 4];
            *(float4*)&rb[0] = *(const float4*)&Bs[kk][tx * 8];
            *(float4*)&rb[4] = *(const float4*)&Bs[kk][tx * 8 + 4];
#pragma unroll
            for (int i = 0; i < 8; i++)
#pragma unroll
                for (int j = 0; j < 8; j++) acc[i][j] += ra[i] * rb[j];
        }
        __syncthreads();
    }

    int col0 = bx * 128 + tx * 8;
#pragma unroll
    for (int i = 0; i < 8; i++) {
#pragma unroll
        for (int j0 = 0; j0 < 8; j0 += 4) {
            float4 o;
            o.x = acc[i][j0 + 0] + bias[col0 + j0 + 0];
            o.y = acc[i][j0 + 1] + bias[col0 + j0 + 1];
            o.z = acc[i][j0 + 2] + bias[col0 + j0 + 2];
            o.w = acc[i][j0 + 3] + bias[col0 + j0 + 3];
            *(float4*)(Cb + (size_t)(ty * 8 + i) * N + tx * 8 + j0) = o;
        }
    }
}

// ---------------------------------------------------------------------------
// Kernel 2: per-row softmax over V, emit PROBABILITIES at extended labels
//           p_ext[row][s]: even s -> p(blank), odd s -> p(target[(s-1)/2])
// ---------------------------------------------------------------------------
__global__ __launch_bounds__(128) void softmax_kernel(const int* __restrict__ target) {
    int warp = threadIdx.x >> 5, lane = threadIdx.x & 31;
    int row = blockIdx.x * 4 + warp;          // 0..16383
    int b = row >> 9;                          // row / 512
    const float* lg = g_logits + (size_t)row * NV;

    float m = -CUDART_INF_F;
    float4 v[8];
#pragma unroll
    for (int i = 0; i < 8; i++) {
        v[i] = *(const float4*)(lg + i * 128 + lane * 4);
        m = fmaxf(m, fmaxf(fmaxf(v[i].x, v[i].y), fmaxf(v[i].z, v[i].w)));
    }
#pragma unroll
    for (int o = 16; o > 0; o >>= 1) m = fmaxf(m, __shfl_xor_sync(0xffffffffu, m, o));

    float se = 0.f;
#pragma unroll
    for (int i = 0; i < 8; i++)
        se += __expf(v[i].x - m) + __expf(v[i].y - m) + __expf(v[i].z - m) + __expf(v[i].w - m);
#pragma unroll
    for (int o = 16; o > 0; o >>= 1) se += __shfl_xor_sync(0xffffffffu, se, o);

    float inv = 1.f / se;
    float pblank = __expf(lg[0] - m) * inv;

    float* P = g_pext + (size_t)row * SPAD;
    const int* tg = target + b * NL;
    for (int j = lane; j < NL; j += 32) {
        int lab = tg[j];
        P[2 * j + 1] = __expf(lg[lab] - m) * inv;
    }
    for (int j = lane; j <= NL; j += 32) P[2 * j] = pblank;
    if (lane < 31) P[NS + lane] = 0.f;   // zero the pad (s = 257..287)
}

// ---------------------------------------------------------------------------
// Kernel 3: CTC forward recursion in probability domain with rescaling.
//           One warp per batch; lane owns 9 contiguous s positions.
// ---------------------------------------------------------------------------
__global__ __launch_bounds__(32) void ctc_kernel(const int* __restrict__ target,
                                                 const int* __restrict__ in_len,
                                                 const int* __restrict__ tgt_len) {
    int b = blockIdx.x;
    int lane = threadIdx.x;
    int s0 = lane * 9;
    const int* tg = target + b * NL;

    // skip flags: odd s >= 3 where target[(s-1)/2] != target[(s-3)/2]
    unsigned skipm = 0;
#pragma unroll
    for (int k = 0; k < 9; k++) {
        int s = s0 + k;
        if (s >= 3 && s < NS && (s & 1)) {
            int j = (s - 1) >> 1;
            if (tg[j] != tg[j - 1]) skipm |= (1u << k);
        }
    }

    const float* P = g_pext + (size_t)b * NT * SPAD;
    int TL = in_len[b];
    int tl = tgt_len[b];
    int send1 = 2 * tl - 1, send2 = 2 * tl;

    float a[9];
#pragma unroll
    for (int k = 0; k < 9; k++) {
        int s = s0 + k;
        float p = (s < NS) ? P[s] : 0.f;
        a[k] = (s < 2) ? p : 0.f;
    }

    float logscale = 0.f;
    float ll = -CUDART_INF_F;

    if (TL == 1) {
        float part = 0.f;
#pragma unroll
        for (int k = 0; k < 9; k++) {
            int s = s0 + k;
            part += (s == send1 || s == send2) ? a[k] : 0.f;
        }
#pragma unroll
        for (int o = 16; o > 0; o >>= 1) part += __shfl_xor_sync(0xffffffffu, part, o);
        ll = __logf(part);
    }

    // prefetch pipeline: pA = p(t), pB = p(t+1)
    float pA[9], pB[9];
#pragma unroll
    for (int k = 0; k < 9; k++) { int s = s0 + k; pA[k] = (s < NS) ? P[SPAD + s] : 0.f; }
#pragma unroll
    for (int k = 0; k < 9; k++) { int s = s0 + k; pB[k] = (s < NS) ? P[2 * SPAD + s] : 0.f; }

    for (int t = 1; t < NT; t++) {
        float pN[9];
        if (t + 2 < NT) {
            const float* Pt = P + (size_t)(t + 2) * SPAD;
#pragma unroll
            for (int k = 0; k < 9; k++) { int s = s0 + k; pN[k] = (s < NS) ? Pt[s] : 0.f; }
        } else {
#pragma unroll
            for (int k = 0; k < 9; k++) pN[k] = 0.f;
        }

        float up1 = __shfl_up_sync(0xffffffffu, a[8], 1);  // s0-1
        float up2 = __shfl_up_sync(0xffffffffu, a[7], 1);  // s0-2
        if (lane == 0) { up1 = 0.f; up2 = 0.f; }

        float na[9];
#pragma unroll
        for (int k = 0; k < 9; k++) {
            float sm1 = (k >= 1) ? a[k - 1] : up1;
            float sm2 = (k >= 2) ? a[k - 2] : ((k == 1) ? up1 : up2);
            float c = a[k] + sm1;
            if ((skipm >> k) & 1u) c += sm2;
            na[k] = c * pA[k];
        }
#pragma unroll
        for (int k = 0; k < 9; k++) a[k] = na[k];

        if (t == TL - 1) {
            float part = 0.f;
#pragma unroll
            for (int k = 0; k < 9; k++) {
                int s = s0 + k;
                part += (s == send1 || s == send2) ? a[k] : 0.f;
            }
#pragma unroll
            for (int o = 16; o > 0; o >>= 1) part += __shfl_xor_sync(0xffffffffu, part, o);
            ll = logscale + __logf(part);
        }

        if ((t & 3) == 3) {
            float tot = 0.f;
#pragma unroll
            for (int k = 0; k < 9; k++) tot += a[k];
#pragma unroll
            for (int o = 16; o > 0; o >>= 1) tot += __shfl_xor_sync(0xffffffffu, tot, o);
            if (tot > 0.f) {
                float sc = 1.f / tot;
                logscale += __logf(tot);
#pragma unroll
                for (int k = 0; k < 9; k++) a[k] *= sc;
            }
        }

#pragma unroll
        for (int k = 0; k < 9; k++) { pA[k] = pB[k]; pB[k] = pN[k]; }
    }

    if (lane == 0) {
        float nll = -ll;
        if (!(nll < 1e29f)) nll = 0.f;   // zero_infinity (also catches NaN)
        g_loss[b] = nll / fmaxf((float)tl, 1.f);
    }
}

// ---------------------------------------------------------------------------
// Kernel 4: mean over batch
// ---------------------------------------------------------------------------
__global__ void reduce_kernel(float* __restrict__ out) {
    int lane = threadIdx.x;
    float v = (lane < NB) ? g_loss[lane] : 0.f;
#pragma unroll
    for (int o = 16; o > 0; o >>= 1) v += __shfl_xor_sync(0xffffffffu, v, o);
    if (lane == 0) out[0] = v * (1.f / NB);
}

extern "C" void kernel_launch(void* const* d_in, const int* in_sizes, int n_in,
                              void* d_out, int out_size) {
    const float* x = (const float*)d_in[0];        // [B,T,D]
    const float* W = (const float*)d_in[1];        // [D,V]
    const float* bias = (const float*)d_in[2];     // [V]
    const int* target = (const int*)d_in[3];       // [B,L]
    const int* in_len = (const int*)d_in[4];       // [B]
    const int* tgt_len = (const int*)d_in[5];      // [B]

    dim3 gg(NV / 128, NM / 128);
    gemm_kernel<<<gg, 256>>>(x, W, bias);
    softmax_kernel<<<NM / 4, 128>>>(target);
    ctc_kernel<<<NB, 32>>>(target, in_len, tgt_len);
    reduce_kernel<<<1, 32>>>((float*)d_out);
}

// round 5
// speedup vs baseline: 2.3053x; 2.3016x over previous
#include <cuda_runtime.h>
#include <cuda_bf16.h>
#include <math_constants.h>
#include <cstdint>

#define NB 32
#define NT 512
#define ND 512
#define NV 1024
#define NL 128
#define NS 257      // 2*NL+1
#define SPAD 288    // padded S stride
#define NM (NB*NT)  // 16384 rows

// Scratch (allocation-free per harness rules)
__device__ float g_logits[(size_t)NM * NV];          // 64 MB
__device__ float g_pext[(size_t)NM * SPAD];          // 18.9 MB
__device__ float g_loss[NB];
__device__ __nv_bfloat16 g_xb[(size_t)NM * ND];      // 16 MB  (x in bf16)
__device__ __nv_bfloat16 g_wt[(size_t)NV * ND];      // 1 MB   (W^T in bf16: [V][D])

// ---------------------------------------------------------------------------
// PTX helpers (portable: cp.async sm_80+, ldmatrix sm_75+, mma.bf16 sm_80+)
// ---------------------------------------------------------------------------
__device__ __forceinline__ uint32_t smem_u32(const void* p) {
    uint32_t a;
    asm("{ .reg .u64 t; cvta.to.shared.u64 t, %1; cvt.u32.u64 %0, t; }" : "=r"(a) : "l"(p));
    return a;
}
#define CP_ASYNC16(dst, src) \
    asm volatile("cp.async.cg.shared.global [%0], [%1], 16;" :: "r"(dst), "l"(src))
#define CP_COMMIT() asm volatile("cp.async.commit_group;" ::: "memory")
#define CP_WAIT1()  asm volatile("cp.async.wait_group 1;" ::: "memory")

#define LDSM_X4(r0, r1, r2, r3, addr) \
    asm volatile("ldmatrix.sync.aligned.m8n8.x4.shared.b16 {%0,%1,%2,%3}, [%4];" \
                 : "=r"(r0), "=r"(r1), "=r"(r2), "=r"(r3) : "r"(addr))

#define MMA16816(d, a0, a1, a2, a3, b0, b1) \
    asm volatile("mma.sync.aligned.m16n8k16.row.col.f32.bf16.bf16.f32 " \
                 "{%0,%1,%2,%3}, {%4,%5,%6,%7}, {%8,%9}, {%0,%1,%2,%3};" \
                 : "+f"((d)[0]), "+f"((d)[1]), "+f"((d)[2]), "+f"((d)[3]) \
                 : "r"(a0), "r"(a1), "r"(a2), "r"(a3), "r"(b0), "r"(b1))

// ---------------------------------------------------------------------------
// Convert x -> bf16
// ---------------------------------------------------------------------------
__global__ __launch_bounds__(256) void convert_x_kernel(const float* __restrict__ x) {
    size_t i = ((size_t)blockIdx.x * 256 + threadIdx.x) * 4;
    float4 v = *(const float4*)(x + i);
    __nv_bfloat162 a = __floats2bfloat162_rn(v.x, v.y);
    __nv_bfloat162 b = __floats2bfloat162_rn(v.z, v.w);
    *(__nv_bfloat162*)(g_xb + i) = a;
    *(__nv_bfloat162*)(g_xb + i + 2) = b;
}

// ---------------------------------------------------------------------------
// Convert + transpose W[D][V] fp32 -> g_wt[V][D] bf16
// ---------------------------------------------------------------------------
__global__ __launch_bounds__(256) void convert_w_kernel(const float* __restrict__ W) {
    __shared__ float t[32][33];
    int tx = threadIdx.x, ty = threadIdx.y;
    int n0 = blockIdx.x * 32, k0 = blockIdx.y * 32;
#pragma unroll
    for (int j = 0; j < 32; j += 8)
        t[ty + j][tx] = W[(size_t)(k0 + ty + j) * NV + n0 + tx];
    __syncthreads();
#pragma unroll
    for (int j = 0; j < 32; j += 8)
        g_wt[(size_t)(n0 + ty + j) * ND + k0 + tx] = __float2bfloat16(t[tx][ty + j]);
}

// ---------------------------------------------------------------------------
// Kernel 1: bf16 HMMA GEMM via mma.sync m16n8k16.
//   CTA tile 128x128, 8 warps (2x4), warp tile 64x32, K stages of 32,
//   cp.async double buffer, smem rows padded to 40 bf16 (80B) -> ldmatrix
//   conflict-free chunk permutation.
// ---------------------------------------------------------------------------
#define KSTAGE 32
#define SROW 40   // padded row stride in bf16 elems (80 bytes)

__global__ __launch_bounds__(256) void gemm_hmma_kernel(const float* __restrict__ bias) {
    __shared__ __align__(16) __nv_bfloat16 sA[2][128 * SROW];
    __shared__ __align__(16) __nv_bfloat16 sB[2][128 * SROW];

    const int tid = threadIdx.x, wid = tid >> 5, lane = tid & 31;
    const int bx = blockIdx.x;           // N tile (0..7)
    const int by = blockIdx.y;           // M tile (0..127)
    const int mBase = by * 128, nBase = bx * 128;
    const int wm = (wid >> 2) * 64;      // warp M offset in tile
    const int wn = (wid & 3) * 32;       // warp N offset in tile

    const __nv_bfloat16* Ag = g_xb + (size_t)mBase * ND;
    const __nv_bfloat16* Bg = g_wt + (size_t)nBase * ND;

    uint32_t sA0 = smem_u32(&sA[0][0]);
    uint32_t sB0 = smem_u32(&sB[0][0]);
    const uint32_t stageBytes = 128 * SROW * 2;

    // per-thread cp.async slots: idx in [0,512): row = idx>>2, chunk = idx&3
    const int ld_r0 = tid >> 2, ld_c0 = (tid & 3);          // slot tid
    const int ld_r1 = (tid + 256) >> 2, ld_c1 = ((tid + 256) & 3);

    // prefetch stage 0
    {
        uint32_t dA = sA0 + ld_r0 * 80 + ld_c0 * 16;
        CP_ASYNC16(dA, Ag + (size_t)ld_r0 * ND + ld_c0 * 8);
        dA = sA0 + ld_r1 * 80 + ld_c1 * 16;
        CP_ASYNC16(dA, Ag + (size_t)ld_r1 * ND + ld_c1 * 8);
        uint32_t dB = sB0 + ld_r0 * 80 + ld_c0 * 16;
        CP_ASYNC16(dB, Bg + (size_t)ld_r0 * ND + ld_c0 * 8);
        dB = sB0 + ld_r1 * 80 + ld_c1 * 16;
        CP_ASYNC16(dB, Bg + (size_t)ld_r1 * ND + ld_c1 * 8);
    }
    CP_COMMIT();

    float acc[4][4][4];
#pragma unroll
    for (int i = 0; i < 4; i++)
#pragma unroll
        for (int j = 0; j < 4; j++)
#pragma unroll
            for (int r = 0; r < 4; r++) acc[i][j][r] = 0.f;

    // precomputed ldmatrix lane address offsets (within a stage, kk=0)
    // A (per mt): row = wm + mt*16 + (lane&15), chunk byte = (lane>>4)*16
    uint32_t aoff = (uint32_t)((wm + (lane & 15)) * 80 + (lane >> 4) * 16);
    // B (per p): n = wn + p*16 + ((lane>>4)&1)*8 + (lane&7), kbyte = ((lane>>3)&1)*16
    uint32_t boff = (uint32_t)((wn + ((lane >> 4) & 1) * 8 + (lane & 7)) * 80 +
                               ((lane >> 3) & 1) * 16);

    const int NSTAGES = ND / KSTAGE;   // 16
#pragma unroll 1
    for (int ks = 0; ks < NSTAGES; ks++) {
        int buf = ks & 1;
        if (ks + 1 < NSTAGES) {
            int nb = buf ^ 1;
            const __nv_bfloat16* Ags = Ag + (ks + 1) * KSTAGE;
            const __nv_bfloat16* Bgs = Bg + (ks + 1) * KSTAGE;
            uint32_t sAn = sA0 + nb * stageBytes;
            uint32_t sBn = sB0 + nb * stageBytes;
            CP_ASYNC16(sAn + ld_r0 * 80 + ld_c0 * 16, Ags + (size_t)ld_r0 * ND + ld_c0 * 8);
            CP_ASYNC16(sAn + ld_r1 * 80 + ld_c1 * 16, Ags + (size_t)ld_r1 * ND + ld_c1 * 8);
            CP_ASYNC16(sBn + ld_r0 * 80 + ld_c0 * 16, Bgs + (size_t)ld_r0 * ND + ld_c0 * 8);
            CP_ASYNC16(sBn + ld_r1 * 80 + ld_c1 * 16, Bgs + (size_t)ld_r1 * ND + ld_c1 * 8);
        }
        CP_COMMIT();
        CP_WAIT1();
        __syncthreads();

        uint32_t sAb = sA0 + buf * stageBytes;
        uint32_t sBb = sB0 + buf * stageBytes;
#pragma unroll
        for (int kk = 0; kk < 2; kk++) {   // two k16 sub-steps per 32-K stage
            uint32_t kbyte = kk * 32;
            uint32_t af[4][4], bf[2][4];
#pragma unroll
            for (int mt = 0; mt < 4; mt++)
                LDSM_X4(af[mt][0], af[mt][1], af[mt][2], af[mt][3],
                        sAb + aoff + mt * 16 * 80 + kbyte);
#pragma unroll
            for (int p = 0; p < 2; p++)
                LDSM_X4(bf[p][0], bf[p][1], bf[p][2], bf[p][3],
                        sBb + boff + p * 16 * 80 + kbyte);
#pragma unroll
            for (int mt = 0; mt < 4; mt++) {
#pragma unroll
                for (int nt = 0; nt < 4; nt++) {
                    int p = nt >> 1, h = (nt & 1) * 2;
                    MMA16816(acc[mt][nt], af[mt][0], af[mt][1], af[mt][2], af[mt][3],
                             bf[p][h], bf[p][h + 1]);
                }
            }
        }
        __syncthreads();
    }

    // epilogue: +bias, store fp32 logits
    const float* bi = bias + nBase + wn;
#pragma unroll
    for (int mt = 0; mt < 4; mt++) {
        int r0 = mBase + wm + mt * 16 + (lane >> 2);
#pragma unroll
        for (int nt = 0; nt < 4; nt++) {
            int c = nt * 8 + (lane & 3) * 2;
            float b0 = bi[c], b1 = bi[c + 1];
            float2 v0 = make_float2(acc[mt][nt][0] + b0, acc[mt][nt][1] + b1);
            float2 v1 = make_float2(acc[mt][nt][2] + b0, acc[mt][nt][3] + b1);
            *(float2*)(g_logits + (size_t)r0 * NV + nBase + wn + c) = v0;
            *(float2*)(g_logits + (size_t)(r0 + 8) * NV + nBase + wn + c) = v1;
        }
    }
}

// ---------------------------------------------------------------------------
// Kernel 2: per-row softmax over V, emit PROBABILITIES at extended labels
// ---------------------------------------------------------------------------
__global__ __launch_bounds__(128) void softmax_kernel(const int* __restrict__ target) {
    int warp = threadIdx.x >> 5, lane = threadIdx.x & 31;
    int row = blockIdx.x * 4 + warp;
    int b = row >> 9;
    const float* lg = g_logits + (size_t)row * NV;

    float m = -CUDART_INF_F;
    float4 v[8];
#pragma unroll
    for (int i = 0; i < 8; i++) {
        v[i] = *(const float4*)(lg + i * 128 + lane * 4);
        m = fmaxf(m, fmaxf(fmaxf(v[i].x, v[i].y), fmaxf(v[i].z, v[i].w)));
    }
#pragma unroll
    for (int o = 16; o > 0; o >>= 1) m = fmaxf(m, __shfl_xor_sync(0xffffffffu, m, o));

    float se = 0.f;
#pragma unroll
    for (int i = 0; i < 8; i++)
        se += __expf(v[i].x - m) + __expf(v[i].y - m) + __expf(v[i].z - m) + __expf(v[i].w - m);
#pragma unroll
    for (int o = 16; o > 0; o >>= 1) se += __shfl_xor_sync(0xffffffffu, se, o);

    float inv = 1.f / se;
    float pblank = __expf(lg[0] - m) * inv;

    float* P = g_pext + (size_t)row * SPAD;
    const int* tg = target + b * NL;
    for (int j = lane; j < NL; j += 32) {
        int lab = tg[j];
        P[2 * j + 1] = __expf(lg[lab] - m) * inv;
    }
    for (int j = lane; j <= NL; j += 32) P[2 * j] = pblank;
    if (lane < 31) P[NS + lane] = 0.f;
}

// ---------------------------------------------------------------------------
// Kernel 3: CTC forward recursion, probability domain with rescaling.
// ---------------------------------------------------------------------------
__global__ __launch_bounds__(32) void ctc_kernel(const int* __restrict__ target,
                                                 const int* __restrict__ in_len,
                                                 const int* __restrict__ tgt_len) {
    int b = blockIdx.x;
    int lane = threadIdx.x;
    int s0 = lane * 9;
    const int* tg = target + b * NL;

    unsigned skipm = 0;
#pragma unroll
    for (int k = 0; k < 9; k++) {
        int s = s0 + k;
        if (s >= 3 && s < NS && (s & 1)) {
            int j = (s - 1) >> 1;
            if (tg[j] != tg[j - 1]) skipm |= (1u << k);
        }
    }

    const float* P = g_pext + (size_t)b * NT * SPAD;
    int TL = in_len[b];
    int tl = tgt_len[b];
    int send1 = 2 * tl - 1, send2 = 2 * tl;

    float a[9];
#pragma unroll
    for (int k = 0; k < 9; k++) {
        int s = s0 + k;
        float p = (s < NS) ? P[s] : 0.f;
        a[k] = (s < 2) ? p : 0.f;
    }

    float logscale = 0.f;
    float ll = -CUDART_INF_F;

    if (TL == 1) {
        float part = 0.f;
#pragma unroll
        for (int k = 0; k < 9; k++) {
            int s = s0 + k;
            part += (s == send1 || s == send2) ? a[k] : 0.f;
        }
#pragma unroll
        for (int o = 16; o > 0; o >>= 1) part += __shfl_xor_sync(0xffffffffu, part, o);
        ll = __logf(part);
    }

    float pA[9], pB[9];
#pragma unroll
    for (int k = 0; k < 9; k++) { int s = s0 + k; pA[k] = (s < NS) ? P[SPAD + s] : 0.f; }
#pragma unroll
    for (int k = 0; k < 9; k++) { int s = s0 + k; pB[k] = (s < NS) ? P[2 * SPAD + s] : 0.f; }

    for (int t = 1; t < NT; t++) {
        float pN[9];
        if (t + 2 < NT) {
            const float* Pt = P + (size_t)(t + 2) * SPAD;
#pragma unroll
            for (int k = 0; k < 9; k++) { int s = s0 + k; pN[k] = (s < NS) ? Pt[s] : 0.f; }
        } else {
#pragma unroll
            for (int k = 0; k < 9; k++) pN[k] = 0.f;
        }

        float up1 = __shfl_up_sync(0xffffffffu, a[8], 1);
        float up2 = __shfl_up_sync(0xffffffffu, a[7], 1);
        if (lane == 0) { up1 = 0.f; up2 = 0.f; }

        float na[9];
#pragma unroll
        for (int k = 0; k < 9; k++) {
            float sm1 = (k >= 1) ? a[k - 1] : up1;
            float sm2 = (k >= 2) ? a[k - 2] : ((k == 1) ? up1 : up2);
            float c = a[k] + sm1;
            if ((skipm >> k) & 1u) c += sm2;
            na[k] = c * pA[k];
        }
#pragma unroll
        for (int k = 0; k < 9; k++) a[k] = na[k];

        if (t == TL - 1) {
            float part = 0.f;
#pragma unroll
            for (int k = 0; k < 9; k++) {
                int s = s0 + k;
                part += (s == send1 || s == send2) ? a[k] : 0.f;
            }
#pragma unroll
            for (int o = 16; o > 0; o >>= 1) part += __shfl_xor_sync(0xffffffffu, part, o);
            ll = logscale + __logf(part);
        }

        if ((t & 3) == 3) {
            float tot = 0.f;
#pragma unroll
            for (int k = 0; k < 9; k++) tot += a[k];
#pragma unroll
            for (int o = 16; o > 0; o >>= 1) tot += __shfl_xor_sync(0xffffffffu, tot, o);
            if (tot > 0.f) {
                float sc = 1.f / tot;
                logscale += __logf(tot);
#pragma unroll
                for (int k = 0; k < 9; k++) a[k] *= sc;
            }
        }

#pragma unroll
        for (int k = 0; k < 9; k++) { pA[k] = pB[k]; pB[k] = pN[k]; }
    }

    if (lane == 0) {
        float nll = -ll;
        if (!(nll < 1e29f)) nll = 0.f;
        g_loss[b] = nll / fmaxf((float)tl, 1.f);
    }
}

// ---------------------------------------------------------------------------
// Kernel 4: mean over batch
// ---------------------------------------------------------------------------
__global__ void reduce_kernel(float* __restrict__ out) {
    int lane = threadIdx.x;
    float v = (lane < NB) ? g_loss[lane] : 0.f;
#pragma unroll
    for (int o = 16; o > 0; o >>= 1) v += __shfl_xor_sync(0xffffffffu, v, o);
    if (lane == 0) out[0] = v * (1.f / NB);
}

extern "C" void kernel_launch(void* const* d_in, const int* in_sizes, int n_in,
                              void* d_out, int out_size) {
    const float* x = (const float*)d_in[0];        // [B,T,D]
    const float* W = (const float*)d_in[1];        // [D,V]
    const float* bias = (const float*)d_in[2];     // [V]
    const int* target = (const int*)d_in[3];       // [B,L]
    const int* in_len = (const int*)d_in[4];       // [B]
    const int* tgt_len = (const int*)d_in[5];      // [B]

    convert_x_kernel<<<(NM * ND) / 4 / 256, 256>>>(x);
    {
        dim3 blk(32, 8), grd(NV / 32, ND / 32);
        convert_w_kernel<<<grd, blk>>>(W);
    }
    {
        dim3 gg(NV / 128, NM / 128);
        gemm_hmma_kernel<<<gg, 256>>>(bias);
    }
    softmax_kernel<<<NM / 4, 128>>>(target);
    ctc_kernel<<<NB, 32>>>(target, in_len, tgt_len);
    reduce_kernel<<<1, 32>>>((float*)d_out);
}

// round 6
// speedup vs baseline: 3.2357x; 1.4036x over previous
#include <cuda_runtime.h>
#include <cuda_bf16.h>
#include <math_constants.h>
#include <cstdint>

#define NB 32
#define NT 512
#define ND 512
#define NV 1024
#define NL 128
#define NS 257      // 2*NL+1
#define SPAD 288    // padded S stride
#define NM (NB*NT)  // 16384 rows

// Scratch (allocation-free per harness rules)
__device__ float g_logits[(size_t)NM * NV];          // 64 MB
__device__ float g_pext[(size_t)NM * SPAD];          // 18.9 MB
__device__ float g_loss[NB];
__device__ __nv_bfloat16 g_xb[(size_t)NM * ND];      // 16 MB  (x in bf16)
__device__ __nv_bfloat16 g_wt[(size_t)NV * ND];      // 1 MB   (W^T in bf16: [V][D])

// ---------------------------------------------------------------------------
// PTX helpers (portable: cp.async sm_80+, ldmatrix sm_75+, mma.bf16 sm_80+)
// ---------------------------------------------------------------------------
__device__ __forceinline__ uint32_t smem_u32(const void* p) {
    uint32_t a;
    asm("{ .reg .u64 t; cvta.to.shared.u64 t, %1; cvt.u32.u64 %0, t; }" : "=r"(a) : "l"(p));
    return a;
}
#define CP_ASYNC16(dst, src) \
    asm volatile("cp.async.cg.shared.global [%0], [%1], 16;" :: "r"(dst), "l"(src))
#define CP_COMMIT() asm volatile("cp.async.commit_group;" ::: "memory")
#define CP_WAIT2()  asm volatile("cp.async.wait_group 2;" ::: "memory")

#define LDSM_X4(r0, r1, r2, r3, addr) \
    asm volatile("ldmatrix.sync.aligned.m8n8.x4.shared.b16 {%0,%1,%2,%3}, [%4];" \
                 : "=r"(r0), "=r"(r1), "=r"(r2), "=r"(r3) : "r"(addr))

#define MMA16816(d, a0, a1, a2, a3, b0, b1) \
    asm volatile("mma.sync.aligned.m16n8k16.row.col.f32.bf16.bf16.f32 " \
                 "{%0,%1,%2,%3}, {%4,%5,%6,%7}, {%8,%9}, {%0,%1,%2,%3};" \
                 : "+f"((d)[0]), "+f"((d)[1]), "+f"((d)[2]), "+f"((d)[3]) \
                 : "r"(a0), "r"(a1), "r"(a2), "r"(a3), "r"(b0), "r"(b1))

// ---------------------------------------------------------------------------
// Convert x -> bf16
// ---------------------------------------------------------------------------
__global__ __launch_bounds__(256) void convert_x_kernel(const float* __restrict__ x) {
    size_t i = ((size_t)blockIdx.x * 256 + threadIdx.x) * 4;
    float4 v = *(const float4*)(x + i);
    __nv_bfloat162 a = __floats2bfloat162_rn(v.x, v.y);
    __nv_bfloat162 b = __floats2bfloat162_rn(v.z, v.w);
    *(__nv_bfloat162*)(g_xb + i) = a;
    *(__nv_bfloat162*)(g_xb + i + 2) = b;
}

// ---------------------------------------------------------------------------
// Convert + transpose W[D][V] fp32 -> g_wt[V][D] bf16
// ---------------------------------------------------------------------------
__global__ __launch_bounds__(256) void convert_w_kernel(const float* __restrict__ W) {
    __shared__ float t[32][33];
    int tx = threadIdx.x, ty = threadIdx.y;
    int n0 = blockIdx.x * 32, k0 = blockIdx.y * 32;
#pragma unroll
    for (int j = 0; j < 32; j += 8)
        t[ty + j][tx] = W[(size_t)(k0 + ty + j) * NV + n0 + tx];
    __syncthreads();
#pragma unroll
    for (int j = 0; j < 32; j += 8)
        g_wt[(size_t)(n0 + ty + j) * ND + k0 + tx] = __float2bfloat16(t[tx][ty + j]);
}

// ---------------------------------------------------------------------------
// Kernel 1: bf16 HMMA GEMM via mma.sync m16n8k16.
//   CTA tile 128x128, 8 warps (2x4), warp tile 64x32, K stages of 32,
//   cp.async 4-stage pipeline, smem rows padded to 40 bf16 (80B).
// ---------------------------------------------------------------------------
#define KSTAGE 32
#define SROW 40           // padded row stride in bf16 elems (80 bytes)
#define PSTAGES 4
#define STAGE_BYTES (128 * SROW * 2)            // 10240 B per tile
#define GEMM_SMEM (PSTAGES * STAGE_BYTES * 2)   // 81920 B total

__global__ __launch_bounds__(256) void gemm_hmma_kernel(const float* __restrict__ bias) {
    extern __shared__ __align__(16) char smem[];

    const int tid = threadIdx.x, wid = tid >> 5, lane = tid & 31;
    const int bx = blockIdx.x;           // N tile (0..7)
    const int by = blockIdx.y;           // M tile (0..127)
    const int mBase = by * 128, nBase = bx * 128;
    const int wm = (wid >> 2) * 64;      // warp M offset in tile
    const int wn = (wid & 3) * 32;       // warp N offset in tile

    const __nv_bfloat16* Ag = g_xb + (size_t)mBase * ND;
    const __nv_bfloat16* Bg = g_wt + (size_t)nBase * ND;

    uint32_t sA0 = smem_u32(smem);
    uint32_t sB0 = sA0 + PSTAGES * STAGE_BYTES;

    // per-thread cp.async slots: idx in [0,512): row = idx>>2, chunk = idx&3
    const int ld_r0 = tid >> 2, ld_c0 = (tid & 3);
    const int ld_r1 = (tid + 256) >> 2, ld_c1 = ((tid + 256) & 3);

    const int NSTAGES = ND / KSTAGE;   // 16

    // prologue: issue stages 0..2
#pragma unroll
    for (int s = 0; s < PSTAGES - 1; s++) {
        const __nv_bfloat16* Ags = Ag + s * KSTAGE;
        const __nv_bfloat16* Bgs = Bg + s * KSTAGE;
        uint32_t sAn = sA0 + s * STAGE_BYTES;
        uint32_t sBn = sB0 + s * STAGE_BYTES;
        CP_ASYNC16(sAn + ld_r0 * 80 + ld_c0 * 16, Ags + (size_t)ld_r0 * ND + ld_c0 * 8);
        CP_ASYNC16(sAn + ld_r1 * 80 + ld_c1 * 16, Ags + (size_t)ld_r1 * ND + ld_c1 * 8);
        CP_ASYNC16(sBn + ld_r0 * 80 + ld_c0 * 16, Bgs + (size_t)ld_r0 * ND + ld_c0 * 8);
        CP_ASYNC16(sBn + ld_r1 * 80 + ld_c1 * 16, Bgs + (size_t)ld_r1 * ND + ld_c1 * 8);
        CP_COMMIT();
    }

    float acc[4][4][4];
#pragma unroll
    for (int i = 0; i < 4; i++)
#pragma unroll
        for (int j = 0; j < 4; j++)
#pragma unroll
            for (int r = 0; r < 4; r++) acc[i][j][r] = 0.f;

    // ldmatrix lane address offsets (within a stage, kk=0)
    uint32_t aoff = (uint32_t)((wm + (lane & 15)) * 80 + (lane >> 4) * 16);
    uint32_t boff = (uint32_t)((wn + ((lane >> 4) & 1) * 8 + (lane & 7)) * 80 +
                               ((lane >> 3) & 1) * 16);

#pragma unroll 1
    for (int ks = 0; ks < NSTAGES; ks++) {
        int buf = ks & (PSTAGES - 1);
        CP_WAIT2();             // stage ks data arrived
        __syncthreads();        // all readers of buf[(ks+3)%4] (stage ks-1) done

        int sf = ks + PSTAGES - 1;      // stage to fetch
        if (sf < NSTAGES) {
            int nb = sf & (PSTAGES - 1);
            const __nv_bfloat16* Ags = Ag + sf * KSTAGE;
            const __nv_bfloat16* Bgs = Bg + sf * KSTAGE;
            uint32_t sAn = sA0 + nb * STAGE_BYTES;
            uint32_t sBn = sB0 + nb * STAGE_BYTES;
            CP_ASYNC16(sAn + ld_r0 * 80 + ld_c0 * 16, Ags + (size_t)ld_r0 * ND + ld_c0 * 8);
            CP_ASYNC16(sAn + ld_r1 * 80 + ld_c1 * 16, Ags + (size_t)ld_r1 * ND + ld_c1 * 8);
            CP_ASYNC16(sBn + ld_r0 * 80 + ld_c0 * 16, Bgs + (size_t)ld_r0 * ND + ld_c0 * 8);
            CP_ASYNC16(sBn + ld_r1 * 80 + ld_c1 * 16, Bgs + (size_t)ld_r1 * ND + ld_c1 * 8);
        }
        CP_COMMIT();            // one group per iteration (may be empty)

        uint32_t sAb = sA0 + buf * STAGE_BYTES;
        uint32_t sBb = sB0 + buf * STAGE_BYTES;
#pragma unroll
        for (int kk = 0; kk < 2; kk++) {
            uint32_t kbyte = kk * 32;
            uint32_t af[4][4], bf[2][4];
#pragma unroll
            for (int mt = 0; mt < 4; mt++)
                LDSM_X4(af[mt][0], af[mt][1], af[mt][2], af[mt][3],
                        sAb + aoff + mt * 16 * 80 + kbyte);
#pragma unroll
            for (int p = 0; p < 2; p++)
                LDSM_X4(bf[p][0], bf[p][1], bf[p][2], bf[p][3],
                        sBb + boff + p * 16 * 80 + kbyte);
#pragma unroll
            for (int mt = 0; mt < 4; mt++) {
#pragma unroll
                for (int nt = 0; nt < 4; nt++) {
                    int p = nt >> 1, h = (nt & 1) * 2;
                    MMA16816(acc[mt][nt], af[mt][0], af[mt][1], af[mt][2], af[mt][3],
                             bf[p][h], bf[p][h + 1]);
                }
            }
        }
    }

    // epilogue: +bias, store fp32 logits
    const float* bi = bias + nBase + wn;
#pragma unroll
    for (int mt = 0; mt < 4; mt++) {
        int r0 = mBase + wm + mt * 16 + (lane >> 2);
#pragma unroll
        for (int nt = 0; nt < 4; nt++) {
            int c = nt * 8 + (lane & 3) * 2;
            float b0 = bi[c], b1 = bi[c + 1];
            float2 v0 = make_float2(acc[mt][nt][0] + b0, acc[mt][nt][1] + b1);
            float2 v1 = make_float2(acc[mt][nt][2] + b0, acc[mt][nt][3] + b1);
            *(float2*)(g_logits + (size_t)r0 * NV + nBase + wn + c) = v0;
            *(float2*)(g_logits + (size_t)(r0 + 8) * NV + nBase + wn + c) = v1;
        }
    }
}

// ---------------------------------------------------------------------------
// Kernel 2: per-row softmax over V, emit PROBABILITIES at extended labels
// ---------------------------------------------------------------------------
__global__ __launch_bounds__(256) void softmax_kernel(const int* __restrict__ target) {
    int warp = threadIdx.x >> 5, lane = threadIdx.x & 31;
    int row = blockIdx.x * 8 + warp;
    int b = row >> 9;
    const float* lg = g_logits + (size_t)row * NV;

    float m = -CUDART_INF_F;
    float4 v[8];
#pragma unroll
    for (int i = 0; i < 8; i++) {
        v[i] = *(const float4*)(lg + i * 128 + lane * 4);
        m = fmaxf(m, fmaxf(fmaxf(v[i].x, v[i].y), fmaxf(v[i].z, v[i].w)));
    }
#pragma unroll
    for (int o = 16; o > 0; o >>= 1) m = fmaxf(m, __shfl_xor_sync(0xffffffffu, m, o));

    float se = 0.f;
#pragma unroll
    for (int i = 0; i < 8; i++)
        se += __expf(v[i].x - m) + __expf(v[i].y - m) + __expf(v[i].z - m) + __expf(v[i].w - m);
#pragma unroll
    for (int o = 16; o > 0; o >>= 1) se += __shfl_xor_sync(0xffffffffu, se, o);

    float inv = 1.f / se;
    float pblank = __expf(lg[0] - m) * inv;

    float* P = g_pext + (size_t)row * SPAD;
    const int* tg = target + b * NL;
    for (int j = lane; j < NL; j += 32) {
        int lab = tg[j];
        P[2 * j + 1] = __expf(lg[lab] - m) * inv;
    }
    for (int j = lane; j <= NL; j += 32) P[2 * j] = pblank;
    if (lane < 31) P[NS + lane] = 0.f;
}

// ---------------------------------------------------------------------------
// Kernel 3: CTC forward recursion, probability domain.
//   Rescale every 8 steps by an exact power of 2 (exponent extraction, no
//   MUFU in the loop). Prefetch depth 7 (t-loop unrolled x7; 511 = 73*7).
// ---------------------------------------------------------------------------
#define CDEPTH 7

__global__ __launch_bounds__(32) void ctc_kernel(const int* __restrict__ target,
                                                 const int* __restrict__ in_len,
                                                 const int* __restrict__ tgt_len) {
    int b = blockIdx.x;
    int lane = threadIdx.x;
    int s0 = lane * 9;
    const int* tg = target + b * NL;

    unsigned skipm = 0;
#pragma unroll
    for (int k = 0; k < 9; k++) {
        int s = s0 + k;
        if (s >= 3 && s < NS && (s & 1)) {
            int j = (s - 1) >> 1;
            if (tg[j] != tg[j - 1]) skipm |= (1u << k);
        }
    }

    const float* P = g_pext + (size_t)b * NT * SPAD;
    int TL = in_len[b];
    int tl = tgt_len[b];
    int send1 = 2 * tl - 1, send2 = 2 * tl;

    float a[9];
#pragma unroll
    for (int k = 0; k < 9; k++) {
        int s = s0 + k;
        float p = (s < NS) ? P[s] : 0.f;
        a[k] = (s < 2) ? p : 0.f;
    }

    int escale = 0;            // true alpha = a * 2^escale
    float ll = -CUDART_INF_F;
    const float LN2 = 0.6931471805599453f;

    if (TL == 1) {
        float part = 0.f;
#pragma unroll
        for (int k = 0; k < 9; k++) {
            int s = s0 + k;
            part += (s == send1 || s == send2) ? a[k] : 0.f;
        }
#pragma unroll
        for (int o = 16; o > 0; o >>= 1) part += __shfl_xor_sync(0xffffffffu, part, o);
        ll = __logf(part);
    }

    // prefetch ring: pf[u] holds p(t) for t = tb+u at loop-block top
    float pf[CDEPTH][9];
#pragma unroll
    for (int u = 0; u < CDEPTH; u++) {
        const float* Pt = P + (size_t)(u + 1) * SPAD;
#pragma unroll
        for (int k = 0; k < 9; k++) { int s = s0 + k; pf[u][k] = (s < NS) ? Pt[s] : 0.f; }
    }

#pragma unroll 1
    for (int tb = 1; tb < NT; tb += CDEPTH) {
#pragma unroll
        for (int u = 0; u < CDEPTH; u++) {
            int t = tb + u;

            float up1 = __shfl_up_sync(0xffffffffu, a[8], 1);
            float up2 = __shfl_up_sync(0xffffffffu, a[7], 1);
            if (lane == 0) { up1 = 0.f; up2 = 0.f; }

            float na[9];
#pragma unroll
            for (int k = 0; k < 9; k++) {
                float sm1 = (k >= 1) ? a[k - 1] : up1;
                float sm2 = (k >= 2) ? a[k - 2] : ((k == 1) ? up1 : up2);
                float c = a[k] + sm1;
                if ((skipm >> k) & 1u) c += sm2;
                na[k] = c * pf[u][k];
            }
#pragma unroll
            for (int k = 0; k < 9; k++) a[k] = na[k];

            if (t == TL - 1) {
                float part = 0.f;
#pragma unroll
                for (int k = 0; k < 9; k++) {
                    int s = s0 + k;
                    part += (s == send1 || s == send2) ? a[k] : 0.f;
                }
#pragma unroll
                for (int o = 16; o > 0; o >>= 1) part += __shfl_xor_sync(0xffffffffu, part, o);
                ll = (float)escale * LN2 + __logf(part);
            }

            if ((t & 7) == 7) {
                float tot = 0.f;
#pragma unroll
                for (int k = 0; k < 9; k++) tot += a[k];
#pragma unroll
                for (int o = 16; o > 0; o >>= 1) tot += __shfl_xor_sync(0xffffffffu, tot, o);
                if (tot > 0.f) {
                    unsigned E = (__float_as_uint(tot) >> 23) & 0xffu;
                    float sc = __uint_as_float((254u - E) << 23);   // exact 2^(127-E)
                    escale += (int)E - 127;
#pragma unroll
                    for (int k = 0; k < 9; k++) a[k] *= sc;
                }
            }

            // prefetch p(t + CDEPTH) into pf[u]
            int tn = t + CDEPTH;
            if (tn < NT) {
                const float* Pt = P + (size_t)tn * SPAD;
#pragma unroll
                for (int k = 0; k < 9; k++) { int s = s0 + k; pf[u][k] = (s < NS) ? Pt[s] : 0.f; }
            } else {
#pragma unroll
                for (int k = 0; k < 9; k++) pf[u][k] = 0.f;
            }
        }
    }

    if (lane == 0) {
        float nll = -ll;
        if (!(nll < 1e29f)) nll = 0.f;
        g_loss[b] = nll / fmaxf((float)tl, 1.f);
    }
}

// ---------------------------------------------------------------------------
// Kernel 4: mean over batch
// ---------------------------------------------------------------------------
__global__ void reduce_kernel(float* __restrict__ out) {
    int lane = threadIdx.x;
    float v = (lane < NB) ? g_loss[lane] : 0.f;
#pragma unroll
    for (int o = 16; o > 0; o >>= 1) v += __shfl_xor_sync(0xffffffffu, v, o);
    if (lane == 0) out[0] = v * (1.f / NB);
}

extern "C" void kernel_launch(void* const* d_in, const int* in_sizes, int n_in,
                              void* d_out, int out_size) {
    const float* x = (const float*)d_in[0];        // [B,T,D]
    const float* W = (const float*)d_in[1];        // [D,V]
    const float* bias = (const float*)d_in[2];     // [V]
    const int* target = (const int*)d_in[3];       // [B,L]
    const int* in_len = (const int*)d_in[4];       // [B]
    const int* tgt_len = (const int*)d_in[5];      // [B]

    static bool attr_set = false;
    if (!attr_set) {
        cudaFuncSetAttribute(gemm_hmma_kernel,
                             cudaFuncAttributeMaxDynamicSharedMemorySize, GEMM_SMEM);
        attr_set = true;
    }

    convert_x_kernel<<<(NM * ND) / 4 / 256, 256>>>(x);
    {
        dim3 blk(32, 8), grd(NV / 32, ND / 32);
        convert_w_kernel<<<grd, blk>>>(W);
    }
    {
        dim3 gg(NV / 128, NM / 128);
        gemm_hmma_kernel<<<gg, 256, GEMM_SMEM>>>(bias);
    }
    softmax_kernel<<<NM / 8, 256>>>(target);
    ctc_kernel<<<NB, 32>>>(target, in_len, tgt_len);
    reduce_kernel<<<1, 32>>>((float*)d_out);
}